// round 9
// baseline (speedup 1.0000x reference)
#include <cuda_runtime.h>
#include <cstdint>

#define B_SZ   64
#define IN_F   8192
#define OUT_F  8192
#define NNZ    262144
#define K8     8
#define SPMM_BLOCKS 740             // 148 SMs * 5 resident blocks
#define UNITS  (OUT_F * 2)          // (row, batch-half) work units

// ---------------- device scratch (no allocations allowed) ----------------
__device__ __align__(16) float  g_t[(size_t)IN_F * B_SZ];   // 2 MB, [col][batch]
__device__ int    g_count[OUT_F];     // zero-init at load; re-zeroed by spmm each call
__device__ int    g_start[OUT_F];
__device__ int    g_cursor[OUT_F];    // after scatter: start + n
__device__ int    g_ticket;           // spmm scheduler; reset by scan
__device__ int    g_c[NNZ];                                  // cols in CSR order
__device__ __align__(16) float g_p[(size_t)NNZ * K8];        // monomial coeffs, CSR order (8MB)

// ---------------- K1: tanh table (smem tile transpose) + row histogram -----
// grid (256,2) = 512 blocks, block (32,8). NO fence, NO fused scan.
__global__ void tanh_hist_kernel(const float* __restrict__ x,
                                 const int*   __restrict__ rows) {
    __shared__ float tile[32][33];
    int tx = threadIdx.x, ty = threadIdx.y;
    int flat = (blockIdx.y * gridDim.x + blockIdx.x) * 256 + ty * 32 + tx;
    int e0 = flat * 2;                 // 512*256*2 == NNZ
    atomicAdd(&g_count[rows[e0]], 1);
    atomicAdd(&g_count[rows[e0 + 1]], 1);

    int c0 = blockIdx.x * 32, b0 = blockIdx.y * 32;
    const float CLIP = 1.0f - 1e-7f;
#pragma unroll
    for (int i = 0; i < 4; i++) {
        int b = b0 + ty + i * 8;
        float xv = x[(size_t)b * IN_F + c0 + tx];
        // fast tanh: 1 - 2/(exp(2x)+1); exact limits, clipped below
        float e  = __expf(2.0f * xv);
        float t  = 1.0f - 2.0f / (e + 1.0f);
        tile[ty + i * 8][tx] = fminf(fmaxf(t, -CLIP), CLIP);
    }
    __syncthreads();
#pragma unroll
    for (int i = 0; i < 4; i++) {
        int c = c0 + ty + i * 8;
        g_t[(size_t)c * B_SZ + b0 + tx] = tile[tx][ty + i * 8]; // coalesced over b
    }
}

// ---------------- K2: exclusive scan over 8192 counters (1 CTA, shfl) ------
__global__ void scan_kernel() {
    int t    = threadIdx.x;        // 0..1023
    int lane = t & 31, wid = t >> 5;
    if (t == 0) g_ticket = 0;      // reset spmm scheduler
    int base = t * 8;
    int v[8];
    int run = 0;
#pragma unroll
    for (int i = 0; i < 8; i++) {
        v[i] = run;
        run += g_count[base + i];
    }
    int x = run;
#pragma unroll
    for (int off = 1; off < 32; off <<= 1) {
        int y = __shfl_up_sync(0xFFFFFFFFu, x, off);
        if (lane >= off) x += y;
    }
    __shared__ int wsum[32];
    if (lane == 31) wsum[wid] = x;
    __syncthreads();
    if (wid == 0) {
        int y = wsum[lane];
#pragma unroll
        for (int off = 1; off < 32; off <<= 1) {
            int z = __shfl_up_sync(0xFFFFFFFFu, y, off);
            if (lane >= off) y += z;
        }
        wsum[lane] = y;
    }
    __syncthreads();
    int warp_excl = (wid > 0) ? wsum[wid - 1] : 0;
    int thr_excl  = warp_excl + (x - run);
#pragma unroll
    for (int i = 0; i < 8; i++) {
        int st = thr_excl + v[i];
        g_start[base + i]  = st;
        g_cursor[base + i] = st;
    }
}

// -------- K3: scatter cols + Chebyshev->monomial coeffs, 4 edges/thread ----
__device__ __forceinline__ void cheb2mono(float4 a, float4 b, float4& p0, float4& p1) {
    p0.x = a.x - a.z + b.x - b.z;
    p0.y = a.y - 3.f*a.w + 5.f*b.y - 7.f*b.w;
    p0.z = 2.f*a.z - 8.f*b.x + 18.f*b.z;
    p0.w = 4.f*a.w - 20.f*b.y + 56.f*b.w;
    p1.x = 8.f*b.x - 48.f*b.z;
    p1.y = 16.f*b.y - 112.f*b.w;
    p1.z = 32.f*b.z;
    p1.w = 64.f*b.w;
}

__global__ void scatter_kernel(const int*   __restrict__ rows,
                               const int*   __restrict__ cols,
                               const float* __restrict__ weight) {
    int i0 = (blockIdx.x * blockDim.x + threadIdx.x) * 4;
    if (i0 >= NNZ) return;
    int4 r4 = *reinterpret_cast<const int4*>(rows + i0);
    int4 c4 = *reinterpret_cast<const int4*>(cols + i0);
    int p0 = atomicAdd(&g_cursor[r4.x], 1);
    int p1 = atomicAdd(&g_cursor[r4.y], 1);
    int p2 = atomicAdd(&g_cursor[r4.z], 1);
    int p3 = atomicAdd(&g_cursor[r4.w], 1);
    const float4* wp = reinterpret_cast<const float4*>(weight + (size_t)i0 * K8);
    int   pos[4] = {p0, p1, p2, p3};
    int   cc[4]  = {c4.x, c4.y, c4.z, c4.w};
#pragma unroll
    for (int k = 0; k < 4; k++) {
        float4 a = wp[2 * k], b = wp[2 * k + 1];
        float4 q0, q1;
        cheb2mono(a, b, q0, q1);
        g_c[pos[k]] = cc[k];
        float4* dst = reinterpret_cast<float4*>(g_p + (size_t)pos[k] * K8);
        dst[0] = q0;
        dst[1] = q1;
    }
}

// ---------------- K4: main SpMM — (row, batch-half) units, 3-stage pipeline
// One warp per unit; lane owns batch bb+lane. t load per edge = one 128B line.
__global__ void __launch_bounds__(256, 5) spmm_kernel(float* __restrict__ out) {
    int lane = threadIdx.x & 31;

    for (;;) {
        int u;
        if (lane == 0) u = atomicAdd(&g_ticket, 1);
        u = __shfl_sync(0xFFFFFFFFu, u, 0);
        if (u >= UNITS) return;
        int r  = u >> 1;
        int bb = (u & 1) << 5;

        int start = g_start[r];
        int n     = g_cursor[r] - start;      // cursor holds start+n after scatter

        const int*   cp    = g_c + start;
        const float* pp    = g_p + (size_t)start * K8;
        const float* tbase = g_t + bb + lane;

        float acc = 0.0f;

        if (n > 0) {
            float tA[8], tB[8];
            float wA0, wA1, wB0, wB1;
            int   cA, cB, cN;
            size_t wmax = (size_t)n * K8 - 1;

#define LC(base_) __ldg(cp + min((base_) + (lane & 7), n - 1))

#define LTW(tb, w0_, w1_, creg, base_)                                           \
    do {                                                                         \
        _Pragma("unroll")                                                        \
        for (int _i = 0; _i < 8; _i++) {                                         \
            int _cc = __shfl_sync(0xFFFFFFFFu, (creg), _i);                      \
            (tb)[_i] = __ldg(tbase + ((size_t)_cc << 6));                        \
        }                                                                        \
        size_t _w0 = (size_t)(base_) * K8 + lane;                                \
        size_t _w1 = _w0 + 32;                                                   \
        (w0_) = __ldg(pp + (_w0 <= wmax ? _w0 : wmax));                          \
        (w1_) = __ldg(pp + (_w1 <= wmax ? _w1 : wmax));                          \
    } while (0)

#define EDGE(tv, wv, _li, gi)                                                    \
    do {                                                                         \
        if ((gi) < n) {                                                          \
            float q0 = __shfl_sync(0xFFFFFFFFu, (wv), (_li) * 8 + 0);            \
            float q1 = __shfl_sync(0xFFFFFFFFu, (wv), (_li) * 8 + 1);            \
            float q2 = __shfl_sync(0xFFFFFFFFu, (wv), (_li) * 8 + 2);            \
            float q3 = __shfl_sync(0xFFFFFFFFu, (wv), (_li) * 8 + 3);            \
            float q4 = __shfl_sync(0xFFFFFFFFu, (wv), (_li) * 8 + 4);            \
            float q5 = __shfl_sync(0xFFFFFFFFu, (wv), (_li) * 8 + 5);            \
            float q6 = __shfl_sync(0xFFFFFFFFu, (wv), (_li) * 8 + 6);            \
            float q7 = __shfl_sync(0xFFFFFFFFu, (wv), (_li) * 8 + 7);            \
            float h = q7;                                                        \
            h = fmaf(h, (tv), q6);                                               \
            h = fmaf(h, (tv), q5);                                               \
            h = fmaf(h, (tv), q4);                                               \
            h = fmaf(h, (tv), q3);                                               \
            h = fmaf(h, (tv), q2);                                               \
            h = fmaf(h, (tv), q1);                                               \
            h = fmaf(h, (tv), q0);                                               \
            acc += h;                                                            \
        }                                                                        \
    } while (0)

#define COMPUTE(tb, w0_, w1_, base_)                                             \
    do {                                                                         \
        EDGE((tb)[0], (w0_), 0, (base_) + 0);                                    \
        EDGE((tb)[1], (w0_), 1, (base_) + 1);                                    \
        EDGE((tb)[2], (w0_), 2, (base_) + 2);                                    \
        EDGE((tb)[3], (w0_), 3, (base_) + 3);                                    \
        EDGE((tb)[4], (w1_), 0, (base_) + 4);                                    \
        EDGE((tb)[5], (w1_), 1, (base_) + 5);                                    \
        EDGE((tb)[6], (w1_), 2, (base_) + 6);                                    \
        EDGE((tb)[7], (w1_), 3, (base_) + 7);                                    \
    } while (0)

            cA = LC(0);
            cB = LC(8);
            LTW(tA, wA0, wA1, cA, 0);
            for (int base = 0; base < n; base += 16) {
                cN = LC(base + 16);
                LTW(tB, wB0, wB1, cB, base + 8);
                COMPUTE(tA, wA0, wA1, base);
                cB = LC(base + 24);
                LTW(tA, wA0, wA1, cN, base + 16);
                COMPUTE(tB, wB0, wB1, base + 8);
            }
#undef LC
#undef LTW
#undef EDGE
#undef COMPUTE
        }

        if (bb == 0 && lane == 0) g_count[r] = 0;   // reset histogram (safe: n from cursor)

        out[(size_t)(bb + lane) * OUT_F + r] = acc;
    }
}

// ---------------- launcher ----------------
extern "C" void kernel_launch(void* const* d_in, const int* in_sizes, int n_in,
                              void* d_out, int out_size) {
    const float* x      = (const float*)d_in[0];   // [64, 8192]
    const float* weight = (const float*)d_in[1];   // [262144, 8]
    const int*   rows   = (const int*)  d_in[2];   // [262144]
    const int*   cols   = (const int*)  d_in[3];   // [262144]
    float*       out    = (float*)d_out;           // [64, 8192]

    dim3 tgrid(IN_F / 32, B_SZ / 32);              // 512 blocks
    dim3 tblk(32, 8);
    tanh_hist_kernel<<<tgrid, tblk>>>(x, rows);
    scan_kernel     <<<1, 1024>>>();
    scatter_kernel  <<<(NNZ / 4 + 255) / 256, 256>>>(rows, cols, weight);
    spmm_kernel     <<<SPMM_BLOCKS, 256>>>(out);
}

// round 10
// speedup vs baseline: 1.1297x; 1.1297x over previous
#include <cuda_runtime.h>
#include <cstdint>

#define B_SZ   64
#define IN_F   8192
#define OUT_F  8192
#define NNZ    262144
#define K8     8
#define SPMM_BLOCKS 740             // 148 SMs * 5 blocks (resident: 4/SM at 61 regs)
#define UNITS  (OUT_F * 2)          // (row, edge-half) work units

// ---------------- device scratch (no allocations allowed) ----------------
__device__ __align__(16) float  g_t[(size_t)IN_F * B_SZ];   // 2 MB, [col][batch]
__device__ int    g_count[OUT_F];     // zero-init at load; re-zeroed by spmm each call
__device__ int    g_start[OUT_F];
__device__ int    g_cursor[OUT_F];    // after scatter: start + n
__device__ int    g_ticket;           // spmm scheduler; reset by scan
__device__ int    g_c[NNZ];                                  // cols in CSR order
__device__ __align__(16) float g_p[(size_t)NNZ * K8];        // monomial coeffs, CSR order (8MB)

// ---------------- K1: tanh table (smem tile transpose) + row histogram -----
// grid (256,2) = 512 blocks, block (32,8). Fast-exp tanh (validated R9).
__global__ void tanh_hist_kernel(const float* __restrict__ x,
                                 const int*   __restrict__ rows) {
    __shared__ float tile[32][33];
    int tx = threadIdx.x, ty = threadIdx.y;
    int flat = (blockIdx.y * gridDim.x + blockIdx.x) * 256 + ty * 32 + tx;
    int e0 = flat * 2;                 // 512*256*2 == NNZ
    atomicAdd(&g_count[rows[e0]], 1);
    atomicAdd(&g_count[rows[e0 + 1]], 1);

    int c0 = blockIdx.x * 32, b0 = blockIdx.y * 32;
    const float CLIP = 1.0f - 1e-7f;
#pragma unroll
    for (int i = 0; i < 4; i++) {
        int b = b0 + ty + i * 8;
        float xv = x[(size_t)b * IN_F + c0 + tx];
        float e  = __expf(2.0f * xv);          // tanh = 1 - 2/(e^{2x}+1)
        float t  = 1.0f - 2.0f / (e + 1.0f);
        tile[ty + i * 8][tx] = fminf(fmaxf(t, -CLIP), CLIP);
    }
    __syncthreads();
#pragma unroll
    for (int i = 0; i < 4; i++) {
        int c = c0 + ty + i * 8;
        g_t[(size_t)c * B_SZ + b0 + tx] = tile[tx][ty + i * 8]; // coalesced over b
    }
}

// ---------------- K2: exclusive scan over 8192 counters (1 CTA, shfl) ------
__global__ void scan_kernel() {
    int t    = threadIdx.x;        // 0..1023
    int lane = t & 31, wid = t >> 5;
    if (t == 0) g_ticket = 0;      // reset spmm scheduler
    int base = t * 8;
    int v[8];
    int run = 0;
#pragma unroll
    for (int i = 0; i < 8; i++) {
        v[i] = run;
        run += g_count[base + i];
    }
    int x = run;
#pragma unroll
    for (int off = 1; off < 32; off <<= 1) {
        int y = __shfl_up_sync(0xFFFFFFFFu, x, off);
        if (lane >= off) x += y;
    }
    __shared__ int wsum[32];
    if (lane == 31) wsum[wid] = x;
    __syncthreads();
    if (wid == 0) {
        int y = wsum[lane];
#pragma unroll
        for (int off = 1; off < 32; off <<= 1) {
            int z = __shfl_up_sync(0xFFFFFFFFu, y, off);
            if (lane >= off) y += z;
        }
        wsum[lane] = y;
    }
    __syncthreads();
    int warp_excl = (wid > 0) ? wsum[wid - 1] : 0;
    int thr_excl  = warp_excl + (x - run);
#pragma unroll
    for (int i = 0; i < 8; i++) {
        int st = thr_excl + v[i];
        g_start[base + i]  = st;
        g_cursor[base + i] = st;
    }
}

// -------- K3: scatter coeffs into CSR order + zero the output buffer -------
__device__ __forceinline__ void cheb2mono(float4 a, float4 b, float4& p0, float4& p1) {
    p0.x = a.x - a.z + b.x - b.z;
    p0.y = a.y - 3.f*a.w + 5.f*b.y - 7.f*b.w;
    p0.z = 2.f*a.z - 8.f*b.x + 18.f*b.z;
    p0.w = 4.f*a.w - 20.f*b.y + 56.f*b.w;
    p1.x = 8.f*b.x - 48.f*b.z;
    p1.y = 16.f*b.y - 112.f*b.w;
    p1.z = 32.f*b.z;
    p1.w = 64.f*b.w;
}

// 65536 threads (256 blocks x 256): 4 edges each + 2 float4 of out zeroing.
__global__ void scatter_kernel(const int*   __restrict__ rows,
                               const int*   __restrict__ cols,
                               const float* __restrict__ weight,
                               float*       __restrict__ out) {
    int tid = blockIdx.x * blockDim.x + threadIdx.x;
    // zero out[64][8192] (524288 floats = 131072 float4; 2 per thread)
    float4 z = make_float4(0.f, 0.f, 0.f, 0.f);
    float4* o4 = reinterpret_cast<float4*>(out);
    o4[tid * 2]     = z;
    o4[tid * 2 + 1] = z;

    int i0 = tid * 4;
    int4 r4 = *reinterpret_cast<const int4*>(rows + i0);
    int4 c4 = *reinterpret_cast<const int4*>(cols + i0);
    int p0 = atomicAdd(&g_cursor[r4.x], 1);
    int p1 = atomicAdd(&g_cursor[r4.y], 1);
    int p2 = atomicAdd(&g_cursor[r4.z], 1);
    int p3 = atomicAdd(&g_cursor[r4.w], 1);
    const float4* wp = reinterpret_cast<const float4*>(weight + (size_t)i0 * K8);
    int   pos[4] = {p0, p1, p2, p3};
    int   cc[4]  = {c4.x, c4.y, c4.z, c4.w};
#pragma unroll
    for (int k = 0; k < 4; k++) {
        float4 a = wp[2 * k], b = wp[2 * k + 1];
        float4 q0, q1;
        cheb2mono(a, b, q0, q1);
        g_c[pos[k]] = cc[k];
        float4* dst = reinterpret_cast<float4*>(g_p + (size_t)pos[k] * K8);
        dst[0] = q0;
        dst[1] = q1;
    }
}

// ---------------- K4: main SpMM — (row, edge-half) units, R7 pipeline ------
// One warp per unit; lane owns batches (2l, 2l+1); edges split across halves
// (no duplicated c/w/shfl work). Halves combine via exactly-2 commutative
// atomic adds per output element (bit-deterministic given zeroed out).
__global__ void __launch_bounds__(256, 4) spmm_kernel(float* __restrict__ out) {
    int lane  = threadIdx.x & 31;
    int lane2 = lane * 2;

    for (;;) {
        int u;
        if (lane == 0) u = atomicAdd(&g_ticket, 1);
        u = __shfl_sync(0xFFFFFFFFu, u, 0);
        if (u >= UNITS) return;
        int r    = u >> 1;
        int half = u & 1;

        int start = g_start[r];
        int nfull = g_cursor[r] - start;      // cursor holds start+n after scatter
        int nh    = (nfull + 1) >> 1;         // first-half size
        int s     = half ? (start + nh) : start;
        int n     = half ? (nfull - nh) : nh;

        if (half == 0 && lane == 0) g_count[r] = 0;   // reset histogram

        const int*   cp = g_c + s;
        const float* pp = g_p + (size_t)s * K8;

        float acc0 = 0.0f, acc1 = 0.0f;

        if (n > 0) {
            float2 tA[8], tB[8];
            float  wA0, wA1, wB0, wB1;
            int    cA, cB, cN;
            size_t wmax = (size_t)n * K8 - 1;

#define LC(base_) __ldg(cp + min((base_) + (lane & 7), n - 1))

#define LTW(tb, w0_, w1_, creg, base_)                                           \
    do {                                                                         \
        _Pragma("unroll")                                                        \
        for (int _i = 0; _i < 8; _i++) {                                         \
            int _cc = __shfl_sync(0xFFFFFFFFu, (creg), _i);                      \
            (tb)[_i] = *reinterpret_cast<const float2*>(                         \
                g_t + ((size_t)_cc << 6) + lane2);                               \
        }                                                                        \
        size_t _w0 = (size_t)(base_) * K8 + lane;                                \
        size_t _w1 = _w0 + 32;                                                   \
        (w0_) = __ldg(pp + (_w0 <= wmax ? _w0 : wmax));                          \
        (w1_) = __ldg(pp + (_w1 <= wmax ? _w1 : wmax));                          \
    } while (0)

#define EDGE(tv, wv, _li, gi)                                                    \
    do {                                                                         \
        if ((gi) < n) {                                                          \
            float q0 = __shfl_sync(0xFFFFFFFFu, (wv), (_li) * 8 + 0);            \
            float q1 = __shfl_sync(0xFFFFFFFFu, (wv), (_li) * 8 + 1);            \
            float q2 = __shfl_sync(0xFFFFFFFFu, (wv), (_li) * 8 + 2);            \
            float q3 = __shfl_sync(0xFFFFFFFFu, (wv), (_li) * 8 + 3);            \
            float q4 = __shfl_sync(0xFFFFFFFFu, (wv), (_li) * 8 + 4);            \
            float q5 = __shfl_sync(0xFFFFFFFFu, (wv), (_li) * 8 + 5);            \
            float q6 = __shfl_sync(0xFFFFFFFFu, (wv), (_li) * 8 + 6);            \
            float q7 = __shfl_sync(0xFFFFFFFFu, (wv), (_li) * 8 + 7);            \
            float tx = (tv).x, ty = (tv).y;                                      \
            float h0 = q7, h1 = q7;                                              \
            h0 = fmaf(h0, tx, q6); h1 = fmaf(h1, ty, q6);                        \
            h0 = fmaf(h0, tx, q5); h1 = fmaf(h1, ty, q5);                        \
            h0 = fmaf(h0, tx, q4); h1 = fmaf(h1, ty, q4);                        \
            h0 = fmaf(h0, tx, q3); h1 = fmaf(h1, ty, q3);                        \
            h0 = fmaf(h0, tx, q2); h1 = fmaf(h1, ty, q2);                        \
            h0 = fmaf(h0, tx, q1); h1 = fmaf(h1, ty, q1);                        \
            h0 = fmaf(h0, tx, q0); h1 = fmaf(h1, ty, q0);                        \
            acc0 += h0; acc1 += h1;                                              \
        }                                                                        \
    } while (0)

#define COMPUTE(tb, w0_, w1_, base_)                                             \
    do {                                                                         \
        EDGE((tb)[0], (w0_), 0, (base_) + 0);                                    \
        EDGE((tb)[1], (w0_), 1, (base_) + 1);                                    \
        EDGE((tb)[2], (w0_), 2, (base_) + 2);                                    \
        EDGE((tb)[3], (w0_), 3, (base_) + 3);                                    \
        EDGE((tb)[4], (w1_), 0, (base_) + 4);                                    \
        EDGE((tb)[5], (w1_), 1, (base_) + 5);                                    \
        EDGE((tb)[6], (w1_), 2, (base_) + 6);                                    \
        EDGE((tb)[7], (w1_), 3, (base_) + 7);                                    \
    } while (0)

            cA = LC(0);
            cB = LC(8);
            LTW(tA, wA0, wA1, cA, 0);
            for (int base = 0; base < n; base += 16) {
                cN = LC(base + 16);
                LTW(tB, wB0, wB1, cB, base + 8);
                COMPUTE(tA, wA0, wA1, base);
                cB = LC(base + 24);
                LTW(tA, wA0, wA1, cN, base + 16);
                COMPUTE(tB, wB0, wB1, base + 8);
            }
#undef LC
#undef LTW
#undef EDGE
#undef COMPUTE
        }

        // exactly two contributions per output element -> order-independent
        atomicAdd(out + (size_t)lane2 * OUT_F + r,       acc0);
        atomicAdd(out + (size_t)(lane2 + 1) * OUT_F + r, acc1);
    }
}

// ---------------- launcher ----------------
extern "C" void kernel_launch(void* const* d_in, const int* in_sizes, int n_in,
                              void* d_out, int out_size) {
    const float* x      = (const float*)d_in[0];   // [64, 8192]
    const float* weight = (const float*)d_in[1];   // [262144, 8]
    const int*   rows   = (const int*)  d_in[2];   // [262144]
    const int*   cols   = (const int*)  d_in[3];   // [262144]
    float*       out    = (float*)d_out;           // [64, 8192]

    dim3 tgrid(IN_F / 32, B_SZ / 32);              // 512 blocks
    dim3 tblk(32, 8);
    tanh_hist_kernel<<<tgrid, tblk>>>(x, rows);
    scan_kernel     <<<1, 1024>>>();
    scatter_kernel  <<<NNZ / 4 / 256, 256>>>(rows, cols, weight, out);
    spmm_kernel     <<<SPMM_BLOCKS, 256>>>(out);
}

// round 11
// speedup vs baseline: 1.2357x; 1.0938x over previous
#include <cuda_runtime.h>
#include <cstdint>

#define B_SZ   64
#define IN_F   8192
#define OUT_F  8192
#define NNZ    262144
#define K8     8
#define SPMM_BLOCKS 740             // 148 SMs * 5 blocks queued (4 resident)

// ---------------- device scratch (no allocations allowed) ----------------
__device__ __align__(16) float  g_t[(size_t)IN_F * B_SZ];   // 2 MB, [col][batch]
__device__ int    g_count[OUT_F];     // zero-init at load; re-zeroed by spmm each call
__device__ int    g_start[OUT_F];
__device__ int    g_cursor[OUT_F];    // after scatter: start + n
__device__ int    g_ticket;           // spmm scheduler; reset by scan
__device__ int    g_c[NNZ];                                  // cols in CSR order
__device__ __align__(16) float g_p[(size_t)NNZ * K8];        // monomial coeffs, CSR order (8MB)

// ---------------- K1: tanh table (smem tile transpose) + row histogram -----
// grid (256,2) = 512 blocks, block (32,8). Fast-exp tanh (validated R9/R10).
__global__ void tanh_hist_kernel(const float* __restrict__ x,
                                 const int*   __restrict__ rows) {
    __shared__ float tile[32][33];
    int tx = threadIdx.x, ty = threadIdx.y;
    int flat = (blockIdx.y * gridDim.x + blockIdx.x) * 256 + ty * 32 + tx;
    int e0 = flat * 2;                 // 512*256*2 == NNZ
    atomicAdd(&g_count[rows[e0]], 1);
    atomicAdd(&g_count[rows[e0 + 1]], 1);

    int c0 = blockIdx.x * 32, b0 = blockIdx.y * 32;
    const float CLIP = 1.0f - 1e-7f;
#pragma unroll
    for (int i = 0; i < 4; i++) {
        int b = b0 + ty + i * 8;
        float xv = x[(size_t)b * IN_F + c0 + tx];
        float e  = __expf(2.0f * xv);          // tanh = 1 - 2/(e^{2x}+1)
        float t  = 1.0f - 2.0f / (e + 1.0f);
        tile[ty + i * 8][tx] = fminf(fmaxf(t, -CLIP), CLIP);
    }
    __syncthreads();
#pragma unroll
    for (int i = 0; i < 4; i++) {
        int c = c0 + ty + i * 8;
        g_t[(size_t)c * B_SZ + b0 + tx] = tile[tx][ty + i * 8]; // coalesced over b
    }
}

// ---------------- K2: exclusive scan over 8192 counters (1 CTA, shfl) ------
__global__ void scan_kernel() {
    int t    = threadIdx.x;        // 0..1023
    int lane = t & 31, wid = t >> 5;
    if (t == 0) g_ticket = 0;      // reset spmm scheduler
    int base = t * 8;
    int v[8];
    int run = 0;
#pragma unroll
    for (int i = 0; i < 8; i++) {
        v[i] = run;
        run += g_count[base + i];
    }
    int x = run;
#pragma unroll
    for (int off = 1; off < 32; off <<= 1) {
        int y = __shfl_up_sync(0xFFFFFFFFu, x, off);
        if (lane >= off) x += y;
    }
    __shared__ int wsum[32];
    if (lane == 31) wsum[wid] = x;
    __syncthreads();
    if (wid == 0) {
        int y = wsum[lane];
#pragma unroll
        for (int off = 1; off < 32; off <<= 1) {
            int z = __shfl_up_sync(0xFFFFFFFFu, y, off);
            if (lane >= off) y += z;
        }
        wsum[lane] = y;
    }
    __syncthreads();
    int warp_excl = (wid > 0) ? wsum[wid - 1] : 0;
    int thr_excl  = warp_excl + (x - run);
#pragma unroll
    for (int i = 0; i < 8; i++) {
        int st = thr_excl + v[i];
        g_start[base + i]  = st;
        g_cursor[base + i] = st;
    }
}

// -------- K3: scatter cols + Chebyshev->monomial coeffs, 4 edges/thread ----
__device__ __forceinline__ void cheb2mono(float4 a, float4 b, float4& p0, float4& p1) {
    p0.x = a.x - a.z + b.x - b.z;
    p0.y = a.y - 3.f*a.w + 5.f*b.y - 7.f*b.w;
    p0.z = 2.f*a.z - 8.f*b.x + 18.f*b.z;
    p0.w = 4.f*a.w - 20.f*b.y + 56.f*b.w;
    p1.x = 8.f*b.x - 48.f*b.z;
    p1.y = 16.f*b.y - 112.f*b.w;
    p1.z = 32.f*b.z;
    p1.w = 64.f*b.w;
}

__global__ void scatter_kernel(const int*   __restrict__ rows,
                               const int*   __restrict__ cols,
                               const float* __restrict__ weight) {
    int i0 = (blockIdx.x * blockDim.x + threadIdx.x) * 4;
    if (i0 >= NNZ) return;
    int4 r4 = *reinterpret_cast<const int4*>(rows + i0);
    int4 c4 = *reinterpret_cast<const int4*>(cols + i0);
    int p0 = atomicAdd(&g_cursor[r4.x], 1);
    int p1 = atomicAdd(&g_cursor[r4.y], 1);
    int p2 = atomicAdd(&g_cursor[r4.z], 1);
    int p3 = atomicAdd(&g_cursor[r4.w], 1);
    const float4* wp = reinterpret_cast<const float4*>(weight + (size_t)i0 * K8);
    int   pos[4] = {p0, p1, p2, p3};
    int   cc[4]  = {c4.x, c4.y, c4.z, c4.w};
#pragma unroll
    for (int k = 0; k < 4; k++) {
        float4 a = wp[2 * k], b = wp[2 * k + 1];
        float4 q0, q1;
        cheb2mono(a, b, q0, q1);
        g_c[pos[k]] = cc[k];
        float4* dst = reinterpret_cast<float4*>(g_p + (size_t)pos[k] * K8);
        dst[0] = q0;
        dst[1] = q1;
    }
}

// ---------------- K4: main SpMM — full-row units, L1-warmed uniform w ------
// One warp per row (dynamic ticket). Lane owns batches (2l, 2l+1).
// c-indices 2 chunks ahead; t 1 chunk ahead (float2/lane); w-chunk lines
// warmed into L1 by a coalesced per-lane load, consumed per-edge via two
// uniform LDG.128 (broadcast, L1 hit) — no shfl in the hot path.
__global__ void __launch_bounds__(256, 4) spmm_kernel(float* __restrict__ out) {
    int lane  = threadIdx.x & 31;
    int lane2 = lane * 2;

    for (;;) {
        int r;
        if (lane == 0) r = atomicAdd(&g_ticket, 1);
        r = __shfl_sync(0xFFFFFFFFu, r, 0);
        if (r >= OUT_F) return;

        int start = g_start[r];
        int n     = g_cursor[r] - start;      // cursor holds start+n after scatter

        if (lane == 0) g_count[r] = 0;        // reset histogram for next call

        const int*   cp = g_c + start;
        const float* pp = g_p + (size_t)start * K8;

        float acc0 = 0.0f, acc1 = 0.0f;

        if (n > 0) {
            float2 tA[8], tB[8];
            float  wA, wB;                    // L1-warming regs (kept alive via asm)
            int    cA, cB, cN;
            size_t wmax = (size_t)n * K8 - 1;

#define LC(base_) __ldg(cp + min((base_) + (lane & 7), n - 1))

// load t for 8 edges (1 chunk ahead) + warm the chunk's w lines into L1
#define LTW(tb, wv, creg, base_)                                                 \
    do {                                                                         \
        _Pragma("unroll")                                                        \
        for (int _i = 0; _i < 8; _i++) {                                         \
            int _cc = __shfl_sync(0xFFFFFFFFu, (creg), _i);                      \
            (tb)[_i] = *reinterpret_cast<const float2*>(                         \
                g_t + ((size_t)_cc << 6) + lane2);                               \
        }                                                                        \
        size_t _w0 = (size_t)(base_) * K8 + lane2;                               \
        (wv) = __ldg(pp + (_w0 <= wmax ? _w0 : wmax));                           \
        asm volatile("" :: "f"(wv));   /* keep warming load alive */             \
    } while (0)

// per-edge: two uniform (broadcast) L1-hit float4 loads + Horner
#define EDGE(tv, gi)                                                             \
    do {                                                                         \
        if ((gi) < n) {                                                          \
            const float4* _u = reinterpret_cast<const float4*>(                  \
                pp + (size_t)(gi) * K8);                                         \
            float4 u0 = __ldg(_u);                                               \
            float4 u1 = __ldg(_u + 1);                                           \
            float tx = (tv).x, ty = (tv).y;                                      \
            float h0 = u1.w, h1 = u1.w;                                          \
            h0 = fmaf(h0, tx, u1.z); h1 = fmaf(h1, ty, u1.z);                    \
            h0 = fmaf(h0, tx, u1.y); h1 = fmaf(h1, ty, u1.y);                    \
            h0 = fmaf(h0, tx, u1.x); h1 = fmaf(h1, ty, u1.x);                    \
            h0 = fmaf(h0, tx, u0.w); h1 = fmaf(h1, ty, u0.w);                    \
            h0 = fmaf(h0, tx, u0.z); h1 = fmaf(h1, ty, u0.z);                    \
            h0 = fmaf(h0, tx, u0.y); h1 = fmaf(h1, ty, u0.y);                    \
            h0 = fmaf(h0, tx, u0.x); h1 = fmaf(h1, ty, u0.x);                    \
            acc0 += h0; acc1 += h1;                                              \
        }                                                                        \
    } while (0)

#define COMPUTE(tb, base_)                                                       \
    do {                                                                         \
        EDGE((tb)[0], (base_) + 0);                                              \
        EDGE((tb)[1], (base_) + 1);                                              \
        EDGE((tb)[2], (base_) + 2);                                              \
        EDGE((tb)[3], (base_) + 3);                                              \
        EDGE((tb)[4], (base_) + 4);                                              \
        EDGE((tb)[5], (base_) + 5);                                              \
        EDGE((tb)[6], (base_) + 6);                                              \
        EDGE((tb)[7], (base_) + 7);                                              \
    } while (0)

            cA = LC(0);
            cB = LC(8);
            LTW(tA, wA, cA, 0);
            for (int base = 0; base < n; base += 16) {
                cN = LC(base + 16);
                LTW(tB, wB, cB, base + 8);
                COMPUTE(tA, base);
                cB = LC(base + 24);
                LTW(tA, wA, cN, base + 16);
                COMPUTE(tB, base + 8);
            }
#undef LC
#undef LTW
#undef EDGE
#undef COMPUTE
        }

        out[(size_t)lane2 * OUT_F + r]       = acc0;
        out[(size_t)(lane2 + 1) * OUT_F + r] = acc1;
    }
}

// ---------------- launcher ----------------
extern "C" void kernel_launch(void* const* d_in, const int* in_sizes, int n_in,
                              void* d_out, int out_size) {
    const float* x      = (const float*)d_in[0];   // [64, 8192]
    const float* weight = (const float*)d_in[1];   // [262144, 8]
    const int*   rows   = (const int*)  d_in[2];   // [262144]
    const int*   cols   = (const int*)  d_in[3];   // [262144]
    float*       out    = (float*)d_out;           // [64, 8192]

    dim3 tgrid(IN_F / 32, B_SZ / 32);              // 512 blocks
    dim3 tblk(32, 8);
    tanh_hist_kernel<<<tgrid, tblk>>>(x, rows);
    scan_kernel     <<<1, 1024>>>();
    scatter_kernel  <<<(NNZ / 4 + 255) / 256, 256>>>(rows, cols, weight);
    spmm_kernel     <<<SPMM_BLOCKS, 256>>>(out);
}